// round 1
// baseline (speedup 1.0000x reference)
#include <cuda_runtime.h>
#include <math.h>

#define Bq   4
#define Sq   2048
#define Dq   512
#define Hq   8
#define DKq  64
#define KN   9
#define BHq  32
#define Mq   8192   /* B*S */
#define EPSN 1e-12f

// ---------------- scratch (device globals; no allocation) ----------------
__device__ float g_q[BHq * Sq * DKq];      // [bh][s][c]
__device__ float g_k[BHq * Sq * DKq];
__device__ float g_v[BHq * Sq * DKq];
__device__ int   g_idx[BHq * Sq * KN];     // top-9 indices, sorted desc by sim
__device__ float g_y[Dq * Mq];             // y^T: [col][b*S + s']
__device__ float g_wt[KN * DKq * DKq];     // Wt[kk][c][o]

// ---------------- Kernel A: QKV GEMM  out = x @ W^T + b, split-head layout ----
__global__ __launch_bounds__(256) void qkv_gemm_kernel(
    const float* __restrict__ x,
    const float* __restrict__ Wq, const float* __restrict__ bq,
    const float* __restrict__ Wk, const float* __restrict__ bk,
    const float* __restrict__ Wv, const float* __restrict__ bv)
{
    __shared__ float As[16][132];
    __shared__ float Bs[16][132];

    const float* W; const float* bias; float* out;
    int z = blockIdx.z;
    if (z == 0)      { W = Wq; bias = bq; out = g_q; }
    else if (z == 1) { W = Wk; bias = bk; out = g_k; }
    else             { W = Wv; bias = bv; out = g_v; }

    int m0 = blockIdx.y * 128;
    int n0 = blockIdx.x * 128;
    int tid = threadIdx.x;
    int tx = tid & 15, ty = tid >> 4;

    float acc[8][8];
#pragma unroll
    for (int i = 0; i < 8; i++)
#pragma unroll
        for (int j = 0; j < 8; j++) acc[i][j] = 0.0f;

    int lrow = tid >> 2;
    int lk   = (tid & 3) * 4;

    for (int k0 = 0; k0 < 512; k0 += 16) {
        float4 a0 = *(const float4*)(x + (size_t)(m0 + lrow)      * 512 + k0 + lk);
        float4 a1 = *(const float4*)(x + (size_t)(m0 + lrow + 64) * 512 + k0 + lk);
        float4 b0 = *(const float4*)(W + (size_t)(n0 + lrow)      * 512 + k0 + lk);
        float4 b1 = *(const float4*)(W + (size_t)(n0 + lrow + 64) * 512 + k0 + lk);
        __syncthreads();
        As[lk+0][lrow] = a0.x; As[lk+1][lrow] = a0.y; As[lk+2][lrow] = a0.z; As[lk+3][lrow] = a0.w;
        As[lk+0][lrow+64] = a1.x; As[lk+1][lrow+64] = a1.y; As[lk+2][lrow+64] = a1.z; As[lk+3][lrow+64] = a1.w;
        Bs[lk+0][lrow] = b0.x; Bs[lk+1][lrow] = b0.y; Bs[lk+2][lrow] = b0.z; Bs[lk+3][lrow] = b0.w;
        Bs[lk+0][lrow+64] = b1.x; Bs[lk+1][lrow+64] = b1.y; Bs[lk+2][lrow+64] = b1.z; Bs[lk+3][lrow+64] = b1.w;
        __syncthreads();
#pragma unroll
        for (int kk = 0; kk < 16; kk++) {
            float a[8], b[8];
#pragma unroll
            for (int i = 0; i < 8; i++) a[i] = As[kk][ty + 16 * i];
#pragma unroll
            for (int j = 0; j < 8; j++) b[j] = Bs[kk][tx + 16 * j];
#pragma unroll
            for (int i = 0; i < 8; i++)
#pragma unroll
                for (int j = 0; j < 8; j++) acc[i][j] = fmaf(a[i], b[j], acc[i][j]);
        }
    }

#pragma unroll
    for (int i = 0; i < 8; i++) {
        int m = m0 + ty + 16 * i;
        int bb = m >> 11;       // / 2048
        int s  = m & 2047;
#pragma unroll
        for (int j = 0; j < 8; j++) {
            int n = n0 + tx + 16 * j;
            int h = n >> 6, c = n & 63;
            out[((size_t)(bb * Hq + h) * Sq + s) * DKq + c] = acc[i][j] + bias[n];
        }
    }
}

// ---------------- Kernel B: L2-normalize q and k rows (over dk=64) ----------
__global__ __launch_bounds__(256) void normalize_kernel()
{
    int gw   = blockIdx.x * 8 + (threadIdx.x >> 5);
    int lane = threadIdx.x & 31;
    float* p;
    if (gw < BHq * Sq) p = g_k + (size_t)gw * 64;
    else               p = g_q + (size_t)(gw - BHq * Sq) * 64;
    float v0 = p[lane], v1 = p[lane + 32];
    float ss = v0 * v0 + v1 * v1;
#pragma unroll
    for (int o = 16; o; o >>= 1) ss += __shfl_xor_sync(0xffffffffu, ss, o);
    float inv = 1.0f / fmaxf(sqrtf(ss), EPSN);
    p[lane] = v0 * inv; p[lane + 32] = v1 * inv;
}

// ---------------- Kernel C: fused sim GEMM + ReLU + streaming top-9 ---------
// grid (S/64, BH); 256 threads. Per block: 64 kn rows vs all 2048 qn cols.
__global__ __launch_bounds__(256) void sim_topk_kernel()
{
    extern __shared__ float sm[];
    float* As = sm;              // [64][65] kn transposed: As[d*65 + r]
    float* Bs = sm + 4160;       // [64][65] qn transposed
    float* Ss = sm + 8320;       // [64][65] sim tile (clamped)

    int bh = blockIdx.y;
    int i0 = blockIdx.x * 64;
    int tid = threadIdx.x;
    int tx = tid & 15, ty = tid >> 4;

    const float* kbase = g_k + (size_t)bh * Sq * DKq;
    const float* qbase = g_q + (size_t)bh * Sq * DKq;

    // load kn tile once
#pragma unroll
    for (int p = 0; p < 4; p++) {
        int f = tid + 256 * p;
        int r = f >> 4, fq = (f & 15) * 4;
        float4 v = *(const float4*)(kbase + (size_t)(i0 + r) * 64 + fq);
        As[(fq + 0) * 65 + r] = v.x;
        As[(fq + 1) * 65 + r] = v.y;
        As[(fq + 2) * 65 + r] = v.z;
        As[(fq + 3) * 65 + r] = v.w;
    }

    float tv[9]; int ti[9];
#pragma unroll
    for (int q = 0; q < 9; q++) { tv[q] = -1.0f; ti[q] = 0; }

    int row2 = tid & 63, part = tid >> 6;

    for (int j0 = 0; j0 < Sq; j0 += 64) {
        __syncthreads();
#pragma unroll
        for (int p = 0; p < 4; p++) {
            int f = tid + 256 * p;
            int r = f >> 4, fq = (f & 15) * 4;
            float4 v = *(const float4*)(qbase + (size_t)(j0 + r) * 64 + fq);
            Bs[(fq + 0) * 65 + r] = v.x;
            Bs[(fq + 1) * 65 + r] = v.y;
            Bs[(fq + 2) * 65 + r] = v.z;
            Bs[(fq + 3) * 65 + r] = v.w;
        }
        __syncthreads();

        float acc[4][4];
#pragma unroll
        for (int i = 0; i < 4; i++)
#pragma unroll
            for (int j = 0; j < 4; j++) acc[i][j] = 0.0f;

#pragma unroll
        for (int d = 0; d < 64; d++) {
            float a[4], b[4];
#pragma unroll
            for (int i = 0; i < 4; i++) a[i] = As[d * 65 + ty + 16 * i];
#pragma unroll
            for (int j = 0; j < 4; j++) b[j] = Bs[d * 65 + tx + 16 * j];
#pragma unroll
            for (int i = 0; i < 4; i++)
#pragma unroll
                for (int j = 0; j < 4; j++) acc[i][j] = fmaf(a[i], b[j], acc[i][j]);
        }
#pragma unroll
        for (int i = 0; i < 4; i++)
#pragma unroll
            for (int j = 0; j < 4; j++)
                Ss[(ty + 16 * i) * 65 + tx + 16 * j] = fmaxf(acc[i][j], 0.0f);
        __syncthreads();

        // streaming top-9 update: this thread covers cols [part*16, part*16+16)
#pragma unroll
        for (int u = 0; u < 16; u++) {
            int c = part * 16 + u;
            float v = Ss[row2 * 65 + c];
            if (v > tv[8]) {
                tv[8] = v; ti[8] = j0 + c;
#pragma unroll
                for (int q = 8; q > 0; q--) {
                    if (tv[q] > tv[q - 1]) {
                        float tf = tv[q]; tv[q] = tv[q - 1]; tv[q - 1] = tf;
                        int tt = ti[q]; ti[q] = ti[q - 1]; ti[q - 1] = tt;
                    }
                }
            }
        }
    }
    __syncthreads();

    // merge 4 per-row lists (alias As/Bs region)
    float* Mv = sm;
    int*   Mi = (int*)(sm + 2304);
#pragma unroll
    for (int q = 0; q < 9; q++) {
        Mv[(row2 * 4 + part) * 9 + q] = tv[q];
        Mi[(row2 * 4 + part) * 9 + q] = ti[q];
    }
    __syncthreads();
    if (tid < 64) {
        int pos0 = 0, pos1 = 0, pos2 = 0, pos3 = 0;
        int obase = (bh * Sq + i0 + tid) * KN;
        for (int kk = 0; kk < KN; kk++) {
            float bv = -2.0f; int bi = 0, bp = 0;
            {
                float v = Mv[(tid * 4 + 0) * 9 + pos0]; int ix = Mi[(tid * 4 + 0) * 9 + pos0];
                if (v > bv || (v == bv && ix < bi)) { bv = v; bi = ix; bp = 0; }
            }
            {
                float v = Mv[(tid * 4 + 1) * 9 + pos1]; int ix = Mi[(tid * 4 + 1) * 9 + pos1];
                if (v > bv || (v == bv && ix < bi)) { bv = v; bi = ix; bp = 1; }
            }
            {
                float v = Mv[(tid * 4 + 2) * 9 + pos2]; int ix = Mi[(tid * 4 + 2) * 9 + pos2];
                if (v > bv || (v == bv && ix < bi)) { bv = v; bi = ix; bp = 2; }
            }
            {
                float v = Mv[(tid * 4 + 3) * 9 + pos3]; int ix = Mi[(tid * 4 + 3) * 9 + pos3];
                if (v > bv || (v == bv && ix < bi)) { bv = v; bi = ix; bp = 3; }
            }
            g_idx[obase + kk] = bi;
            if (bp == 0) pos0++; else if (bp == 1) pos1++; else if (bp == 2) pos2++; else pos3++;
        }
    }
}

// ---------------- prep: transpose conv_w [o][c][kk] -> Wt[kk][c][o] ---------
__global__ void transpose_convw_kernel(const float* __restrict__ w)
{
    int t = blockIdx.x * 256 + threadIdx.x;
    if (t < KN * DKq * DKq) {
        int o = t & 63, c = (t >> 6) & 63, kk = t >> 12;
        g_wt[t] = w[(o * 64 + c) * KN + kk];
    }
}

// ---------------- Kernel D: gather v by idx + grouped conv, scatter to y^T --
// grid (S/32, BH); 128 threads; dynamic smem.
__global__ __launch_bounds__(128) void conv_kernel(const float* __restrict__ convb)
{
    extern __shared__ float smd[];
    float* v_s  = smd;                   // [288][64]
    float* w_s  = smd + 288 * 64;        // [64 c][64 o]
    int*   sidx = (int*)(smd + 288 * 64 + 4096);  // [288]

    int bh = blockIdx.y;
    int i0 = blockIdx.x * 32;
    int b  = bh >> 3, h = bh & 7;
    int tid = threadIdx.x;

    for (int t = tid; t < 288; t += 128)
        sidx[t] = g_idx[(bh * Sq + i0 + t / KN) * KN + (t % KN)];
    __syncthreads();

    const float* vbase = g_v + (size_t)bh * Sq * DKq;
    for (int p = 0; p < 36; p++) {
        int f = tid + 128 * p;           // 4608 float4s total
        int r = f >> 4, fq = (f & 15) * 4;
        int j = sidx[r];
        float4 vv = *(const float4*)(vbase + (size_t)j * 64 + fq);
        *(float4*)&v_s[r * 64 + fq] = vv;
    }

    int og = tid & 15; int o0 = og * 4;
    int ig = tid >> 4;                    // 0..7 -> 4 i's each
    float acc[4][4];
#pragma unroll
    for (int t = 0; t < 4; t++)
#pragma unroll
        for (int j = 0; j < 4; j++) acc[t][j] = 0.0f;

    for (int kk = 0; kk < KN; kk++) {
        __syncthreads();
#pragma unroll
        for (int p = 0; p < 8; p++) {
            int f = tid + 128 * p;        // float4 index < 1024
            *(float4*)&w_s[f * 4] = *(const float4*)(g_wt + kk * 4096 + f * 4);
        }
        __syncthreads();
#pragma unroll 4
        for (int c = 0; c < 64; c++) {
            float4 w4 = *(const float4*)&w_s[c * 64 + o0];
#pragma unroll
            for (int t = 0; t < 4; t++) {
                float vv = v_s[(((ig * 4 + t) * KN) + kk) * 64 + c];
                acc[t][0] = fmaf(vv, w4.x, acc[t][0]);
                acc[t][1] = fmaf(vv, w4.y, acc[t][1]);
                acc[t][2] = fmaf(vv, w4.z, acc[t][2]);
                acc[t][3] = fmaf(vv, w4.w, acc[t][3]);
            }
        }
    }

    float4 cb = *(const float4*)(convb + o0);
    int colbase = (h * 64 + (i0 >> 5)) * Mq + b * Sq;   // d' = i0/32 constant per block
#pragma unroll
    for (int t = 0; t < 4; t++) {
        int il = ig * 4 + t;
        int sp = ((i0 + il) & 31) * 64 + o0;            // s' = (i%32)*64 + o
        float4 o;
        o.x = acc[t][0] + cb.x;
        o.y = acc[t][1] + cb.y;
        o.z = acc[t][2] + cb.z;
        o.w = acc[t][3] + cb.w;
        *(float4*)&g_y[colbase + sp] = o;
    }
}

// ---------------- Kernel E: final = y @ Wo^T + b (A = g_y^T, column-major) --
__global__ __launch_bounds__(256) void out_gemm_kernel(
    const float* __restrict__ Wo, const float* __restrict__ bo,
    float* __restrict__ outp)
{
    __shared__ float As[16][132];
    __shared__ float Bs[16][132];

    int m0 = blockIdx.y * 128, n0 = blockIdx.x * 128;
    int tid = threadIdx.x, tx = tid & 15, ty = tid >> 4;

    float acc[8][8];
#pragma unroll
    for (int i = 0; i < 8; i++)
#pragma unroll
        for (int j = 0; j < 8; j++) acc[i][j] = 0.0f;

    int lrow = tid >> 2, lk = (tid & 3) * 4;
    int fk = tid >> 5, fm = tid & 31;

    for (int k0 = 0; k0 < 512; k0 += 16) {
        float4 a0 = *(const float4*)(g_y + (size_t)(k0 + fk)     * Mq + m0 + fm * 4);
        float4 a1 = *(const float4*)(g_y + (size_t)(k0 + fk + 8) * Mq + m0 + fm * 4);
        float4 b0 = *(const float4*)(Wo + (size_t)(n0 + lrow)      * 512 + k0 + lk);
        float4 b1 = *(const float4*)(Wo + (size_t)(n0 + lrow + 64) * 512 + k0 + lk);
        __syncthreads();
        *(float4*)&As[fk][fm * 4]     = a0;
        *(float4*)&As[fk + 8][fm * 4] = a1;
        Bs[lk+0][lrow] = b0.x; Bs[lk+1][lrow] = b0.y; Bs[lk+2][lrow] = b0.z; Bs[lk+3][lrow] = b0.w;
        Bs[lk+0][lrow+64] = b1.x; Bs[lk+1][lrow+64] = b1.y; Bs[lk+2][lrow+64] = b1.z; Bs[lk+3][lrow+64] = b1.w;
        __syncthreads();
#pragma unroll
        for (int kk = 0; kk < 16; kk++) {
            float a[8], b[8];
#pragma unroll
            for (int i = 0; i < 8; i++) a[i] = As[kk][ty + 16 * i];
#pragma unroll
            for (int j = 0; j < 8; j++) b[j] = Bs[kk][tx + 16 * j];
#pragma unroll
            for (int i = 0; i < 8; i++)
#pragma unroll
                for (int j = 0; j < 8; j++) acc[i][j] = fmaf(a[i], b[j], acc[i][j]);
        }
    }
#pragma unroll
    for (int i = 0; i < 8; i++) {
        int m = m0 + ty + 16 * i;
#pragma unroll
        for (int j = 0; j < 8; j++) {
            int n = n0 + tx + 16 * j;
            outp[(size_t)m * 512 + n] = acc[i][j] + bo[n];
        }
    }
}

// ---------------- launch -----------------------------------------------------
extern "C" void kernel_launch(void* const* d_in, const int* in_sizes, int n_in,
                              void* d_out, int out_size)
{
    (void)in_sizes; (void)n_in; (void)out_size;
    const float* x      = (const float*)d_in[0];
    const float* Wq_w   = (const float*)d_in[1];
    const float* Wq_b   = (const float*)d_in[2];
    const float* Wk_w   = (const float*)d_in[3];
    const float* Wk_b   = (const float*)d_in[4];
    const float* Wv_w   = (const float*)d_in[5];
    const float* Wv_b   = (const float*)d_in[6];
    const float* Wo_w   = (const float*)d_in[7];
    const float* Wo_b   = (const float*)d_in[8];
    const float* conv_w = (const float*)d_in[9];
    const float* conv_b = (const float*)d_in[10];
    float* outp = (float*)d_out;

    const int SMEM_C = 3 * 64 * 65 * 4;                 // 49920 B
    const int SMEM_D = (288 * 64 + 64 * 64) * 4 + 288 * 4;  // 91264 B
    cudaFuncSetAttribute(sim_topk_kernel, cudaFuncAttributeMaxDynamicSharedMemorySize, SMEM_C);
    cudaFuncSetAttribute(conv_kernel,     cudaFuncAttributeMaxDynamicSharedMemorySize, SMEM_D);

    qkv_gemm_kernel<<<dim3(4, 64, 3), 256>>>(x, Wq_w, Wq_b, Wk_w, Wk_b, Wv_w, Wv_b);
    normalize_kernel<<<16384, 256>>>();
    transpose_convw_kernel<<<144, 256>>>(conv_w);
    sim_topk_kernel<<<dim3(32, 32), 256, SMEM_C>>>();
    conv_kernel<<<dim3(64, 32), 128, SMEM_D>>>(conv_b);
    out_gemm_kernel<<<dim3(4, 64), 256>>>(Wo_w, Wo_b, outp);
}

// round 2
// speedup vs baseline: 1.0156x; 1.0156x over previous
#include <cuda_runtime.h>
#include <math.h>

#define Bq   4
#define Sq   2048
#define Dq   512
#define Hq   8
#define DKq  64
#define KN   9
#define BHq  32
#define Mq   8192   /* B*S */
#define EPSN 1e-12f

// ---------------- packed fp32x2 helpers (sm_103a FFMA2) ----------------
__device__ __forceinline__ unsigned long long pack2(float x) {
    unsigned long long r;
    asm("mov.b64 %0, {%1, %1};" : "=l"(r) : "f"(x));
    return r;
}
__device__ __forceinline__ void fma2(unsigned long long& d,
                                     unsigned long long a, unsigned long long b) {
    asm("fma.rn.f32x2 %0, %1, %2, %0;" : "+l"(d) : "l"(a), "l"(b));
}
__device__ __forceinline__ float lo32(unsigned long long v) {
    return __uint_as_float((unsigned)v);
}
__device__ __forceinline__ float hi32(unsigned long long v) {
    return __uint_as_float((unsigned)(v >> 32));
}

// ---------------- scratch (device globals; no allocation) ----------------
__device__ float g_q[BHq * Sq * DKq];      // [bh][s][c]
__device__ float g_k[BHq * Sq * DKq];
__device__ float g_v[BHq * Sq * DKq];
__device__ int   g_idx[BHq * Sq * KN];     // top-9 indices, sorted desc by sim
__device__ float g_y[Dq * Mq];             // y^T: [col][b*S + s']
__device__ float g_wt[KN * DKq * DKq];     // Wt[kk][c][o]

// ---------------- Kernel A: QKV GEMM  out = x @ W^T + b, split-head layout ----
__global__ __launch_bounds__(256) void qkv_gemm_kernel(
    const float* __restrict__ x,
    const float* __restrict__ Wq, const float* __restrict__ bq,
    const float* __restrict__ Wk, const float* __restrict__ bk,
    const float* __restrict__ Wv, const float* __restrict__ bv)
{
    __shared__ __align__(16) float As[16][132];
    __shared__ __align__(16) float Bs[16][132];

    const float* W; const float* bias; float* out;
    int z = blockIdx.z;
    if (z == 0)      { W = Wq; bias = bq; out = g_q; }
    else if (z == 1) { W = Wk; bias = bk; out = g_k; }
    else             { W = Wv; bias = bv; out = g_v; }

    int m0 = blockIdx.y * 128;
    int n0 = blockIdx.x * 128;
    int tid = threadIdx.x;
    int tx = tid & 15, ty = tid >> 4;
    int r0 = ty * 8, c0 = tx * 8;

    unsigned long long acc[8][4];
#pragma unroll
    for (int i = 0; i < 8; i++)
#pragma unroll
        for (int j = 0; j < 4; j++) acc[i][j] = 0ULL;

    int lrow = tid >> 2;
    int lk   = (tid & 3) * 4;

    for (int k0 = 0; k0 < 512; k0 += 16) {
        float4 a0 = *(const float4*)(x + (size_t)(m0 + lrow)      * 512 + k0 + lk);
        float4 a1 = *(const float4*)(x + (size_t)(m0 + lrow + 64) * 512 + k0 + lk);
        float4 b0 = *(const float4*)(W + (size_t)(n0 + lrow)      * 512 + k0 + lk);
        float4 b1 = *(const float4*)(W + (size_t)(n0 + lrow + 64) * 512 + k0 + lk);
        __syncthreads();
        As[lk+0][lrow] = a0.x; As[lk+1][lrow] = a0.y; As[lk+2][lrow] = a0.z; As[lk+3][lrow] = a0.w;
        As[lk+0][lrow+64] = a1.x; As[lk+1][lrow+64] = a1.y; As[lk+2][lrow+64] = a1.z; As[lk+3][lrow+64] = a1.w;
        Bs[lk+0][lrow] = b0.x; Bs[lk+1][lrow] = b0.y; Bs[lk+2][lrow] = b0.z; Bs[lk+3][lrow] = b0.w;
        Bs[lk+0][lrow+64] = b1.x; Bs[lk+1][lrow+64] = b1.y; Bs[lk+2][lrow+64] = b1.z; Bs[lk+3][lrow+64] = b1.w;
        __syncthreads();
#pragma unroll
        for (int kk = 0; kk < 16; kk++) {
            float4 av0 = *(const float4*)&As[kk][r0];
            float4 av1 = *(const float4*)&As[kk][r0 + 4];
            ulonglong2 bb0 = *(const ulonglong2*)&Bs[kk][c0];
            ulonglong2 bb1 = *(const ulonglong2*)&Bs[kk][c0 + 4];
            unsigned long long a2[8];
            a2[0] = pack2(av0.x); a2[1] = pack2(av0.y); a2[2] = pack2(av0.z); a2[3] = pack2(av0.w);
            a2[4] = pack2(av1.x); a2[5] = pack2(av1.y); a2[6] = pack2(av1.z); a2[7] = pack2(av1.w);
#pragma unroll
            for (int i = 0; i < 8; i++) {
                fma2(acc[i][0], a2[i], bb0.x);
                fma2(acc[i][1], a2[i], bb0.y);
                fma2(acc[i][2], a2[i], bb1.x);
                fma2(acc[i][3], a2[i], bb1.y);
            }
        }
    }

    float4 bias0 = *(const float4*)(bias + n0 + c0);
    float4 bias1 = *(const float4*)(bias + n0 + c0 + 4);
    int n = n0 + c0;
    int h = n >> 6, c = n & 63;
#pragma unroll
    for (int i = 0; i < 8; i++) {
        int m = m0 + r0 + i;
        int bb = m >> 11;       // / 2048
        int s  = m & 2047;
        float4 o0, o1;
        o0.x = lo32(acc[i][0]) + bias0.x;
        o0.y = hi32(acc[i][0]) + bias0.y;
        o0.z = lo32(acc[i][1]) + bias0.z;
        o0.w = hi32(acc[i][1]) + bias0.w;
        o1.x = lo32(acc[i][2]) + bias1.x;
        o1.y = hi32(acc[i][2]) + bias1.y;
        o1.z = lo32(acc[i][3]) + bias1.z;
        o1.w = hi32(acc[i][3]) + bias1.w;
        float* po = out + ((size_t)(bb * Hq + h) * Sq + s) * DKq + c;
        *(float4*)po = o0;
        *(float4*)(po + 4) = o1;
    }
}

// ---------------- Kernel B: L2-normalize q and k rows (over dk=64) ----------
__global__ __launch_bounds__(256) void normalize_kernel()
{
    int gw   = blockIdx.x * 8 + (threadIdx.x >> 5);
    int lane = threadIdx.x & 31;
    float* p;
    if (gw < BHq * Sq) p = g_k + (size_t)gw * 64;
    else               p = g_q + (size_t)(gw - BHq * Sq) * 64;
    float v0 = p[lane], v1 = p[lane + 32];
    float ss = v0 * v0 + v1 * v1;
#pragma unroll
    for (int o = 16; o; o >>= 1) ss += __shfl_xor_sync(0xffffffffu, ss, o);
    float inv = 1.0f / fmaxf(sqrtf(ss), EPSN);
    p[lane] = v0 * inv; p[lane + 32] = v1 * inv;
}

// ---------------- Kernel C: fused sim GEMM + ReLU + streaming top-9 ---------
// grid (S/128, BH); 256 threads. Per block: 128 kn rows vs all 2048 qn cols.
// As/Bs: d-major 64x128, XOR-swizzled (bits 3-5 of row index by (d>>2)&7).
__global__ __launch_bounds__(256) void sim_topk_kernel()
{
    extern __shared__ __align__(16) float sm[];
    float* As = sm;              // 64*128
    float* Bs = sm + 8192;       // 64*128
    float* Ss = sm + 16384;      // 128*132

    int bh = blockIdx.y;
    int i0 = blockIdx.x * 128;
    int tid = threadIdx.x;
    int tx = tid & 15, ty = tid >> 4;
    int r0 = ty * 8, c0 = tx * 8;

    const float* kbase = g_k + (size_t)bh * Sq * DKq;
    const float* qbase = g_q + (size_t)bh * Sq * DKq;

    // fill As (kn tile, transposed + swizzled), once
#pragma unroll
    for (int p = 0; p < 8; p++) {
        int f = tid + 256 * p;
        int r = f >> 4, dq = (f & 15) * 4;
        float4 v = *(const float4*)(kbase + (size_t)(i0 + r) * 64 + dq);
        int pr = r ^ (((dq >> 2) & 7) << 3);
        As[(dq + 0) * 128 + pr] = v.x;
        As[(dq + 1) * 128 + pr] = v.y;
        As[(dq + 2) * 128 + pr] = v.z;
        As[(dq + 3) * 128 + pr] = v.w;
    }

    float tv[9]; int ti[9];
#pragma unroll
    for (int q = 0; q < 9; q++) { tv[q] = -1.0f; ti[q] = 0; }

    int row = tid >> 1, part = tid & 1;

    for (int j0 = 0; j0 < Sq; j0 += 128) {
        __syncthreads();
        // fill Bs (qn tile, transposed + swizzled)
#pragma unroll
        for (int p = 0; p < 8; p++) {
            int f = tid + 256 * p;
            int r = f >> 4, dq = (f & 15) * 4;
            float4 v = *(const float4*)(qbase + (size_t)(j0 + r) * 64 + dq);
            int pr = r ^ (((dq >> 2) & 7) << 3);
            Bs[(dq + 0) * 128 + pr] = v.x;
            Bs[(dq + 1) * 128 + pr] = v.y;
            Bs[(dq + 2) * 128 + pr] = v.z;
            Bs[(dq + 3) * 128 + pr] = v.w;
        }
        __syncthreads();

        unsigned long long acc[8][4];
#pragma unroll
        for (int i = 0; i < 8; i++)
#pragma unroll
            for (int j = 0; j < 4; j++) acc[i][j] = 0ULL;

#pragma unroll 4
        for (int kk = 0; kk < 64; kk++) {
            int swz = ((kk >> 2) & 7) << 3;
            float4 av0 = *(const float4*)&As[kk * 128 + (r0 ^ swz)];
            float4 av1 = *(const float4*)&As[kk * 128 + (r0 ^ swz) + 4];
            ulonglong2 bb0 = *(const ulonglong2*)&Bs[kk * 128 + (c0 ^ swz)];
            ulonglong2 bb1 = *(const ulonglong2*)&Bs[kk * 128 + (c0 ^ swz) + 4];
            unsigned long long a2[8];
            a2[0] = pack2(av0.x); a2[1] = pack2(av0.y); a2[2] = pack2(av0.z); a2[3] = pack2(av0.w);
            a2[4] = pack2(av1.x); a2[5] = pack2(av1.y); a2[6] = pack2(av1.z); a2[7] = pack2(av1.w);
#pragma unroll
            for (int i = 0; i < 8; i++) {
                fma2(acc[i][0], a2[i], bb0.x);
                fma2(acc[i][1], a2[i], bb0.y);
                fma2(acc[i][2], a2[i], bb1.x);
                fma2(acc[i][3], a2[i], bb1.y);
            }
        }
        // write ReLU'd tile
#pragma unroll
        for (int i = 0; i < 8; i++) {
            float4 o0, o1;
            o0.x = fmaxf(lo32(acc[i][0]), 0.0f);
            o0.y = fmaxf(hi32(acc[i][0]), 0.0f);
            o0.z = fmaxf(lo32(acc[i][1]), 0.0f);
            o0.w = fmaxf(hi32(acc[i][1]), 0.0f);
            o1.x = fmaxf(lo32(acc[i][2]), 0.0f);
            o1.y = fmaxf(hi32(acc[i][2]), 0.0f);
            o1.z = fmaxf(lo32(acc[i][3]), 0.0f);
            o1.w = fmaxf(hi32(acc[i][3]), 0.0f);
            *(float4*)&Ss[(r0 + i) * 132 + c0] = o0;
            *(float4*)&Ss[(r0 + i) * 132 + c0 + 4] = o1;
        }
        __syncthreads();

        // streaming top-9: this thread covers cols [part*64, part*64+64)
#pragma unroll
        for (int t = 0; t < 16; t++) {
            float4 v4 = *(const float4*)&Ss[row * 132 + part * 64 + t * 4];
            int cb = j0 + part * 64 + t * 4;
            float vv[4] = {v4.x, v4.y, v4.z, v4.w};
#pragma unroll
            for (int u = 0; u < 4; u++) {
                float v = vv[u];
                if (v > tv[8]) {
                    tv[8] = v; ti[8] = cb + u;
#pragma unroll
                    for (int q = 8; q > 0; q--) {
                        if (tv[q] > tv[q - 1]) {
                            float tf = tv[q]; tv[q] = tv[q - 1]; tv[q - 1] = tf;
                            int tt = ti[q]; ti[q] = ti[q - 1]; ti[q - 1] = tt;
                        }
                    }
                }
            }
        }
    }
    __syncthreads();

    // merge 2 per-row lists (alias As/Bs region)
    float* Mv = sm;                      // 256*9 floats
    int*   Mi = (int*)(sm + 2304);       // 256*9 ints
#pragma unroll
    for (int q = 0; q < 9; q++) {
        Mv[(row * 2 + part) * 9 + q] = tv[q];
        Mi[(row * 2 + part) * 9 + q] = ti[q];
    }
    __syncthreads();
    if (tid < 128) {
        int p0 = 0, p1 = 0;
        const float* L0v = Mv + (tid * 2) * 9;
        const float* L1v = Mv + (tid * 2 + 1) * 9;
        const int*   L0i = Mi + (tid * 2) * 9;
        const int*   L1i = Mi + (tid * 2 + 1) * 9;
        int obase = (bh * Sq + i0 + tid) * KN;
#pragma unroll
        for (int kk = 0; kk < KN; kk++) {
            float v0 = L0v[p0], v1 = L1v[p1];
            int ix0 = L0i[p0], ix1 = L1i[p1];
            bool take0 = (v0 > v1) || (v0 == v1 && ix0 < ix1);
            g_idx[obase + kk] = take0 ? ix0 : ix1;
            if (take0) p0++; else p1++;
        }
    }
}

// ---------------- prep: transpose conv_w [o][c][kk] -> Wt[kk][c][o] ---------
__global__ void transpose_convw_kernel(const float* __restrict__ w)
{
    int t = blockIdx.x * 256 + threadIdx.x;
    if (t < KN * DKq * DKq) {
        int o = t & 63, c = (t >> 6) & 63, kk = t >> 12;
        g_wt[t] = w[(o * 64 + c) * KN + kk];
    }
}

// ---------------- Kernel D: gather v by idx + grouped conv, scatter to y^T --
// grid (S/32, BH); 128 threads; dynamic smem.
__global__ __launch_bounds__(128) void conv_kernel(const float* __restrict__ convb)
{
    extern __shared__ float smd[];
    float* v_s  = smd;                   // [288][64]
    float* w_s  = smd + 288 * 64;        // [64 c][64 o]
    int*   sidx = (int*)(smd + 288 * 64 + 4096);  // [288]

    int bh = blockIdx.y;
    int i0 = blockIdx.x * 32;
    int b  = bh >> 3, h = bh & 7;
    int tid = threadIdx.x;

    for (int t = tid; t < 288; t += 128)
        sidx[t] = g_idx[(bh * Sq + i0 + t / KN) * KN + (t % KN)];
    __syncthreads();

    const float* vbase = g_v + (size_t)bh * Sq * DKq;
    for (int p = 0; p < 36; p++) {
        int f = tid + 128 * p;           // 4608 float4s total
        int r = f >> 4, fq = (f & 15) * 4;
        int j = sidx[r];
        float4 vv = *(const float4*)(vbase + (size_t)j * 64 + fq);
        *(float4*)&v_s[r * 64 + fq] = vv;
    }

    int og = tid & 15; int o0 = og * 4;
    int ig = tid >> 4;                    // 0..7 -> 4 i's each
    unsigned long long acc[4][2];
#pragma unroll
    for (int t = 0; t < 4; t++) { acc[t][0] = 0ULL; acc[t][1] = 0ULL; }

    for (int kk = 0; kk < KN; kk++) {
        __syncthreads();
#pragma unroll
        for (int p = 0; p < 8; p++) {
            int f = tid + 128 * p;        // float4 index < 1024
            *(float4*)&w_s[f * 4] = *(const float4*)(g_wt + kk * 4096 + f * 4);
        }
        __syncthreads();
#pragma unroll 4
        for (int c = 0; c < 64; c++) {
            ulonglong2 wp = *(const ulonglong2*)&w_s[c * 64 + o0];
#pragma unroll
            for (int t = 0; t < 4; t++) {
                unsigned long long v2 = pack2(v_s[(((ig * 4 + t) * KN) + kk) * 64 + c]);
                fma2(acc[t][0], v2, wp.x);
                fma2(acc[t][1], v2, wp.y);
            }
        }
    }

    float4 cb = *(const float4*)(convb + o0);
    int colbase = (h * 64 + (i0 >> 5)) * Mq + b * Sq;   // d' = i0/32 constant per block
#pragma unroll
    for (int t = 0; t < 4; t++) {
        int il = ig * 4 + t;
        int sp = ((i0 + il) & 31) * 64 + o0;            // s' = (i%32)*64 + o
        float4 o;
        o.x = lo32(acc[t][0]) + cb.x;
        o.y = hi32(acc[t][0]) + cb.y;
        o.z = lo32(acc[t][1]) + cb.z;
        o.w = hi32(acc[t][1]) + cb.w;
        *(float4*)&g_y[colbase + sp] = o;
    }
}

// ---------------- Kernel E: final = y @ Wo^T + b (A = g_y^T, column-major) --
__global__ __launch_bounds__(256) void out_gemm_kernel(
    const float* __restrict__ Wo, const float* __restrict__ bo,
    float* __restrict__ outp)
{
    __shared__ __align__(16) float As[16][132];
    __shared__ __align__(16) float Bs[16][132];

    int m0 = blockIdx.y * 128, n0 = blockIdx.x * 128;
    int tid = threadIdx.x, tx = tid & 15, ty = tid >> 4;
    int r0 = ty * 8, c0 = tx * 8;

    unsigned long long acc[8][4];
#pragma unroll
    for (int i = 0; i < 8; i++)
#pragma unroll
        for (int j = 0; j < 4; j++) acc[i][j] = 0ULL;

    int lrow = tid >> 2, lk = (tid & 3) * 4;
    int fk = tid >> 5, fm = tid & 31;

    for (int k0 = 0; k0 < 512; k0 += 16) {
        float4 a0 = *(const float4*)(g_y + (size_t)(k0 + fk)     * Mq + m0 + fm * 4);
        float4 a1 = *(const float4*)(g_y + (size_t)(k0 + fk + 8) * Mq + m0 + fm * 4);
        float4 b0 = *(const float4*)(Wo + (size_t)(n0 + lrow)      * 512 + k0 + lk);
        float4 b1 = *(const float4*)(Wo + (size_t)(n0 + lrow + 64) * 512 + k0 + lk);
        __syncthreads();
        *(float4*)&As[fk][fm * 4]     = a0;
        *(float4*)&As[fk + 8][fm * 4] = a1;
        Bs[lk+0][lrow] = b0.x; Bs[lk+1][lrow] = b0.y; Bs[lk+2][lrow] = b0.z; Bs[lk+3][lrow] = b0.w;
        Bs[lk+0][lrow+64] = b1.x; Bs[lk+1][lrow+64] = b1.y; Bs[lk+2][lrow+64] = b1.z; Bs[lk+3][lrow+64] = b1.w;
        __syncthreads();
#pragma unroll
        for (int kk = 0; kk < 16; kk++) {
            float4 av0 = *(const float4*)&As[kk][r0];
            float4 av1 = *(const float4*)&As[kk][r0 + 4];
            ulonglong2 bb0 = *(const ulonglong2*)&Bs[kk][c0];
            ulonglong2 bb1 = *(const ulonglong2*)&Bs[kk][c0 + 4];
            unsigned long long a2[8];
            a2[0] = pack2(av0.x); a2[1] = pack2(av0.y); a2[2] = pack2(av0.z); a2[3] = pack2(av0.w);
            a2[4] = pack2(av1.x); a2[5] = pack2(av1.y); a2[6] = pack2(av1.z); a2[7] = pack2(av1.w);
#pragma unroll
            for (int i = 0; i < 8; i++) {
                fma2(acc[i][0], a2[i], bb0.x);
                fma2(acc[i][1], a2[i], bb0.y);
                fma2(acc[i][2], a2[i], bb1.x);
                fma2(acc[i][3], a2[i], bb1.y);
            }
        }
    }

    float4 bias0 = *(const float4*)(bo + n0 + c0);
    float4 bias1 = *(const float4*)(bo + n0 + c0 + 4);
#pragma unroll
    for (int i = 0; i < 8; i++) {
        int m = m0 + r0 + i;
        float4 o0, o1;
        o0.x = lo32(acc[i][0]) + bias0.x;
        o0.y = hi32(acc[i][0]) + bias0.y;
        o0.z = lo32(acc[i][1]) + bias0.z;
        o0.w = hi32(acc[i][1]) + bias0.w;
        o1.x = lo32(acc[i][2]) + bias1.x;
        o1.y = hi32(acc[i][2]) + bias1.y;
        o1.z = lo32(acc[i][3]) + bias1.z;
        o1.w = hi32(acc[i][3]) + bias1.w;
        float* po = outp + (size_t)m * 512 + n0 + c0;
        *(float4*)po = o0;
        *(float4*)(po + 4) = o1;
    }
}

// ---------------- launch -----------------------------------------------------
extern "C" void kernel_launch(void* const* d_in, const int* in_sizes, int n_in,
                              void* d_out, int out_size)
{
    (void)in_sizes; (void)n_in; (void)out_size;
    const float* x      = (const float*)d_in[0];
    const float* Wq_w   = (const float*)d_in[1];
    const float* Wq_b   = (const float*)d_in[2];
    const float* Wk_w   = (const float*)d_in[3];
    const float* Wk_b   = (const float*)d_in[4];
    const float* Wv_w   = (const float*)d_in[5];
    const float* Wv_b   = (const float*)d_in[6];
    const float* Wo_w   = (const float*)d_in[7];
    const float* Wo_b   = (const float*)d_in[8];
    const float* conv_w = (const float*)d_in[9];
    const float* conv_b = (const float*)d_in[10];
    float* outp = (float*)d_out;

    const int SMEM_C = (64 * 128 * 2 + 128 * 132) * 4;      // 133120 B
    const int SMEM_D = (288 * 64 + 64 * 64) * 4 + 288 * 4;  // 91264 B
    cudaFuncSetAttribute(sim_topk_kernel, cudaFuncAttributeMaxDynamicSharedMemorySize, SMEM_C);
    cudaFuncSetAttribute(conv_kernel,     cudaFuncAttributeMaxDynamicSharedMemorySize, SMEM_D);

    qkv_gemm_kernel<<<dim3(4, 64, 3), 256>>>(x, Wq_w, Wq_b, Wk_w, Wk_b, Wv_w, Wv_b);
    normalize_kernel<<<16384, 256>>>();
    transpose_convw_kernel<<<144, 256>>>(conv_w);
    sim_topk_kernel<<<dim3(16, 32), 256, SMEM_C>>>();
    conv_kernel<<<dim3(64, 32), 128, SMEM_D>>>(conv_b);
    out_gemm_kernel<<<dim3(4, 64), 256>>>(Wo_w, Wo_b, outp);
}

// round 3
// speedup vs baseline: 1.1315x; 1.1141x over previous
#include <cuda_runtime.h>
#include <math.h>

#define Bq   4
#define Sq   2048
#define Dq   512
#define Hq   8
#define DKq  64
#define KN   9
#define BHq  32
#define Mq   8192   /* B*S */
#define EPSN 1e-12f

// ---------------- packed fp32x2 helpers (sm_103a FFMA2) ----------------
__device__ __forceinline__ unsigned long long pack2(float x) {
    unsigned long long r;
    asm("mov.b64 %0, {%1, %1};" : "=l"(r) : "f"(x));
    return r;
}
__device__ __forceinline__ void fma2(unsigned long long& d,
                                     unsigned long long a, unsigned long long b) {
    asm("fma.rn.f32x2 %0, %1, %2, %0;" : "+l"(d) : "l"(a), "l"(b));
}
__device__ __forceinline__ float lo32(unsigned long long v) {
    return __uint_as_float((unsigned)v);
}
__device__ __forceinline__ float hi32(unsigned long long v) {
    return __uint_as_float((unsigned)(v >> 32));
}

// ---------------- scratch (device globals; no allocation) ----------------
__device__ float g_q[BHq * Sq * DKq];      // [bh][s][c]
__device__ float g_k[BHq * Sq * DKq];
__device__ float g_v[BHq * Sq * DKq];
__device__ int   g_idx[BHq * Sq * KN];     // top-9 indices, sorted desc by sim
__device__ float g_y[Dq * Mq];             // y^T: [col][b*S + s']
__device__ float g_wt[KN * DKq * DKq];     // Wt[kk][c][o]

// ---------------- Kernel A: QKV GEMM  out = x @ W^T + b, split-head layout ----
__global__ __launch_bounds__(256, 2) void qkv_gemm_kernel(
    const float* __restrict__ x,
    const float* __restrict__ Wq, const float* __restrict__ bq,
    const float* __restrict__ Wk, const float* __restrict__ bk,
    const float* __restrict__ Wv, const float* __restrict__ bv)
{
    __shared__ __align__(16) float As[16][132];
    __shared__ __align__(16) float Bs[16][132];

    const float* W; const float* bias; float* out;
    int z = blockIdx.z;
    if (z == 0)      { W = Wq; bias = bq; out = g_q; }
    else if (z == 1) { W = Wk; bias = bk; out = g_k; }
    else             { W = Wv; bias = bv; out = g_v; }

    int m0 = blockIdx.y * 128;
    int n0 = blockIdx.x * 128;
    int tid = threadIdx.x;
    int tx = tid & 15, ty = tid >> 4;
    int r0 = ty * 8, c0 = tx * 8;

    // acc[p][j]: rows (r0+2p, r0+2p+1) packed in lanes, col c0+j
    unsigned long long acc[4][8];
#pragma unroll
    for (int i = 0; i < 4; i++)
#pragma unroll
        for (int j = 0; j < 8; j++) acc[i][j] = 0ULL;

    int lrow = tid >> 2;
    int lk   = (tid & 3) * 4;

    for (int k0 = 0; k0 < 512; k0 += 16) {
        float4 a0 = *(const float4*)(x + (size_t)(m0 + lrow)      * 512 + k0 + lk);
        float4 a1 = *(const float4*)(x + (size_t)(m0 + lrow + 64) * 512 + k0 + lk);
        float4 b0 = *(const float4*)(W + (size_t)(n0 + lrow)      * 512 + k0 + lk);
        float4 b1 = *(const float4*)(W + (size_t)(n0 + lrow + 64) * 512 + k0 + lk);
        __syncthreads();
        As[lk+0][lrow] = a0.x; As[lk+1][lrow] = a0.y; As[lk+2][lrow] = a0.z; As[lk+3][lrow] = a0.w;
        As[lk+0][lrow+64] = a1.x; As[lk+1][lrow+64] = a1.y; As[lk+2][lrow+64] = a1.z; As[lk+3][lrow+64] = a1.w;
        Bs[lk+0][lrow] = b0.x; Bs[lk+1][lrow] = b0.y; Bs[lk+2][lrow] = b0.z; Bs[lk+3][lrow] = b0.w;
        Bs[lk+0][lrow+64] = b1.x; Bs[lk+1][lrow+64] = b1.y; Bs[lk+2][lrow+64] = b1.z; Bs[lk+3][lrow+64] = b1.w;
        __syncthreads();
#pragma unroll
        for (int kk = 0; kk < 16; kk++) {
            ulonglong2 ap0 = *(const ulonglong2*)&As[kk][r0];
            ulonglong2 ap1 = *(const ulonglong2*)&As[kk][r0 + 4];
            float4 bv0 = *(const float4*)&Bs[kk][c0];
            float4 bv1 = *(const float4*)&Bs[kk][c0 + 4];
            unsigned long long b2[8];
            b2[0] = pack2(bv0.x); b2[1] = pack2(bv0.y); b2[2] = pack2(bv0.z); b2[3] = pack2(bv0.w);
            b2[4] = pack2(bv1.x); b2[5] = pack2(bv1.y); b2[6] = pack2(bv1.z); b2[7] = pack2(bv1.w);
            unsigned long long a2[4] = {ap0.x, ap0.y, ap1.x, ap1.y};
#pragma unroll
            for (int i = 0; i < 4; i++)
#pragma unroll
                for (int j = 0; j < 8; j++) fma2(acc[i][j], a2[i], b2[j]);
        }
    }

    float4 bias0 = *(const float4*)(bias + n0 + c0);
    float4 bias1 = *(const float4*)(bias + n0 + c0 + 4);
    int n = n0 + c0;
    int h = n >> 6, c = n & 63;
#pragma unroll
    for (int i = 0; i < 4; i++) {
#pragma unroll
        for (int half = 0; half < 2; half++) {
            int m = m0 + r0 + 2 * i + half;
            int bb = m >> 11;
            int s  = m & 2047;
            float4 o0, o1;
            if (half == 0) {
                o0.x = lo32(acc[i][0]) + bias0.x; o0.y = lo32(acc[i][1]) + bias0.y;
                o0.z = lo32(acc[i][2]) + bias0.z; o0.w = lo32(acc[i][3]) + bias0.w;
                o1.x = lo32(acc[i][4]) + bias1.x; o1.y = lo32(acc[i][5]) + bias1.y;
                o1.z = lo32(acc[i][6]) + bias1.z; o1.w = lo32(acc[i][7]) + bias1.w;
            } else {
                o0.x = hi32(acc[i][0]) + bias0.x; o0.y = hi32(acc[i][1]) + bias0.y;
                o0.z = hi32(acc[i][2]) + bias0.z; o0.w = hi32(acc[i][3]) + bias0.w;
                o1.x = hi32(acc[i][4]) + bias1.x; o1.y = hi32(acc[i][5]) + bias1.y;
                o1.z = hi32(acc[i][6]) + bias1.z; o1.w = hi32(acc[i][7]) + bias1.w;
            }
            float* po = out + ((size_t)(bb * Hq + h) * Sq + s) * DKq + c;
            *(float4*)po = o0;
            *(float4*)(po + 4) = o1;
        }
    }
}

// ---------------- Kernel B: L2-normalize q and k rows (over dk=64) ----------
__global__ __launch_bounds__(256) void normalize_kernel()
{
    int gw   = blockIdx.x * 8 + (threadIdx.x >> 5);
    int lane = threadIdx.x & 31;
    float* p;
    if (gw < BHq * Sq) p = g_k + (size_t)gw * 64;
    else               p = g_q + (size_t)(gw - BHq * Sq) * 64;
    float v0 = p[lane], v1 = p[lane + 32];
    float ss = v0 * v0 + v1 * v1;
#pragma unroll
    for (int o = 16; o; o >>= 1) ss += __shfl_xor_sync(0xffffffffu, ss, o);
    float inv = 1.0f / fmaxf(sqrtf(ss), EPSN);
    p[lane] = v0 * inv; p[lane + 32] = v1 * inv;
}

// ---------------- Kernel C: fused sim GEMM + ReLU + streaming top-9 ---------
// grid (S/128, BH); 256 threads; 2 blocks/SM. Per block: 128 kn rows vs 2048 qn.
// j-tile = 64. As: d-major 64x128 swizzled; Bs: d-major 64x64 swizzled.
__global__ __launch_bounds__(256, 2) void sim_topk_kernel()
{
    extern __shared__ __align__(16) float sm[];
    float* As = sm;              // 64*128 = 8192
    float* Bs = sm + 8192;       // 64*64  = 4096
    float* Ss = sm + 12288;      // 128*68 = 8704

    int bh = blockIdx.y;
    int i0 = blockIdx.x * 128;
    int tid = threadIdx.x;
    int tx = tid & 15, ty = tid >> 4;
    int r0 = ty * 8, c0 = tx * 4;

    const float* kbase = g_k + (size_t)bh * Sq * DKq;
    const float* qbase = g_q + (size_t)bh * Sq * DKq;

    // fill As (kn tile, transposed + swizzled), once
#pragma unroll
    for (int p = 0; p < 8; p++) {
        int f = tid + 256 * p;
        int r = f >> 4, dq = (f & 15) * 4;
        float4 v = *(const float4*)(kbase + (size_t)(i0 + r) * 64 + dq);
        int pr = r ^ (((dq >> 2) & 7) << 3);
        As[(dq + 0) * 128 + pr] = v.x;
        As[(dq + 1) * 128 + pr] = v.y;
        As[(dq + 2) * 128 + pr] = v.z;
        As[(dq + 3) * 128 + pr] = v.w;
    }

    float tv[9]; int ti[9];
#pragma unroll
    for (int q = 0; q < 9; q++) { tv[q] = -1.0f; ti[q] = 0; }

    int row = tid >> 1, part = tid & 1;

    for (int j0 = 0; j0 < Sq; j0 += 64) {
        __syncthreads();
        // fill Bs (qn tile, transposed + swizzled): 64 j-rows x 64 d
#pragma unroll
        for (int p = 0; p < 4; p++) {
            int f = tid + 256 * p;
            int r = f >> 4, dq = (f & 15) * 4;
            float4 v = *(const float4*)(qbase + (size_t)(j0 + r) * 64 + dq);
            int pr = r ^ (((dq >> 2) & 7) << 3);
            Bs[(dq + 0) * 64 + pr] = v.x;
            Bs[(dq + 1) * 64 + pr] = v.y;
            Bs[(dq + 2) * 64 + pr] = v.z;
            Bs[(dq + 3) * 64 + pr] = v.w;
        }
        __syncthreads();

        // acc[p][j]: rows (r0+2p, r0+2p+1) in lanes, col c0+j
        unsigned long long acc[4][4];
#pragma unroll
        for (int i = 0; i < 4; i++)
#pragma unroll
            for (int j = 0; j < 4; j++) acc[i][j] = 0ULL;

#pragma unroll 8
        for (int kk = 0; kk < 64; kk++) {
            int swz = ((kk >> 2) & 7) << 3;
            ulonglong2 ap0 = *(const ulonglong2*)&As[kk * 128 + (r0 ^ swz)];
            ulonglong2 ap1 = *(const ulonglong2*)&As[kk * 128 + (r0 ^ swz) + 4];
            float4 bv = *(const float4*)&Bs[kk * 64 + (c0 ^ swz)];
            unsigned long long b2[4];
            b2[0] = pack2(bv.x); b2[1] = pack2(bv.y);
            b2[2] = pack2(bv.z); b2[3] = pack2(bv.w);
            unsigned long long a2[4] = {ap0.x, ap0.y, ap1.x, ap1.y};
#pragma unroll
            for (int i = 0; i < 4; i++)
#pragma unroll
                for (int j = 0; j < 4; j++) fma2(acc[i][j], a2[i], b2[j]);
        }

        // write ReLU'd tile: rows r0..r0+7, cols c0..c0+3
#pragma unroll
        for (int i = 0; i < 4; i++) {
            float4 oL, oH;
            oL.x = fmaxf(lo32(acc[i][0]), 0.0f);
            oL.y = fmaxf(lo32(acc[i][1]), 0.0f);
            oL.z = fmaxf(lo32(acc[i][2]), 0.0f);
            oL.w = fmaxf(lo32(acc[i][3]), 0.0f);
            oH.x = fmaxf(hi32(acc[i][0]), 0.0f);
            oH.y = fmaxf(hi32(acc[i][1]), 0.0f);
            oH.z = fmaxf(hi32(acc[i][2]), 0.0f);
            oH.w = fmaxf(hi32(acc[i][3]), 0.0f);
            *(float4*)&Ss[(r0 + 2 * i)     * 68 + c0] = oL;
            *(float4*)&Ss[(r0 + 2 * i + 1) * 68 + c0] = oH;
        }
        __syncthreads();

        // streaming top-9: this thread covers cols [part*32, part*32+32)
#pragma unroll
        for (int t = 0; t < 8; t++) {
            float4 v4 = *(const float4*)&Ss[row * 68 + part * 32 + t * 4];
            int cb = j0 + part * 32 + t * 4;
            float vv[4] = {v4.x, v4.y, v4.z, v4.w};
#pragma unroll
            for (int u = 0; u < 4; u++) {
                float v = vv[u];
                if (v > tv[8]) {
                    tv[8] = v; ti[8] = cb + u;
#pragma unroll
                    for (int q = 8; q > 0; q--) {
                        if (tv[q] > tv[q - 1]) {
                            float tf = tv[q]; tv[q] = tv[q - 1]; tv[q - 1] = tf;
                            int tt = ti[q]; ti[q] = ti[q - 1]; ti[q - 1] = tt;
                        }
                    }
                }
            }
        }
    }
    __syncthreads();

    // merge 2 per-row lists (alias As region)
    float* Mv = sm;                      // 256*9 floats
    int*   Mi = (int*)(sm + 2304);       // 256*9 ints
#pragma unroll
    for (int q = 0; q < 9; q++) {
        Mv[(row * 2 + part) * 9 + q] = tv[q];
        Mi[(row * 2 + part) * 9 + q] = ti[q];
    }
    __syncthreads();
    if (tid < 128) {
        int p0 = 0, p1 = 0;
        const float* L0v = Mv + (tid * 2) * 9;
        const float* L1v = Mv + (tid * 2 + 1) * 9;
        const int*   L0i = Mi + (tid * 2) * 9;
        const int*   L1i = Mi + (tid * 2 + 1) * 9;
        int obase = (bh * Sq + i0 + tid) * KN;
#pragma unroll
        for (int kk = 0; kk < KN; kk++) {
            float v0 = L0v[p0], v1 = L1v[p1];
            int ix0 = L0i[p0], ix1 = L1i[p1];
            bool take0 = (v0 > v1) || (v0 == v1 && ix0 < ix1);
            g_idx[obase + kk] = take0 ? ix0 : ix1;
            if (take0) p0++; else p1++;
        }
    }
}

// ---------------- prep: transpose conv_w [o][c][kk] -> Wt[kk][c][o] ---------
__global__ void transpose_convw_kernel(const float* __restrict__ w)
{
    int t = blockIdx.x * 256 + threadIdx.x;
    if (t < KN * DKq * DKq) {
        int o = t & 63, c = (t >> 6) & 63, kk = t >> 12;
        g_wt[t] = w[(o * 64 + c) * KN + kk];
    }
}

// ---------------- Kernel D: gather v by idx + grouped conv, scatter to y^T --
// grid (S/32, BH); 128 threads; dynamic smem.
__global__ __launch_bounds__(128, 2) void conv_kernel(const float* __restrict__ convb)
{
    extern __shared__ float smd[];
    float* v_s  = smd;                   // [288][64]
    float* w_s  = smd + 288 * 64;        // [64 c][64 o]
    int*   sidx = (int*)(smd + 288 * 64 + 4096);  // [288]

    int bh = blockIdx.y;
    int i0 = blockIdx.x * 32;
    int b  = bh >> 3, h = bh & 7;
    int tid = threadIdx.x;

    for (int t = tid; t < 288; t += 128)
        sidx[t] = g_idx[(bh * Sq + i0 + t / KN) * KN + (t % KN)];
    __syncthreads();

    const float* vbase = g_v + (size_t)bh * Sq * DKq;
    for (int p = 0; p < 36; p++) {
        int f = tid + 128 * p;           // 4608 float4s total
        int r = f >> 4, fq = (f & 15) * 4;
        int j = sidx[r];
        float4 vv = *(const float4*)(vbase + (size_t)j * 64 + fq);
        *(float4*)&v_s[r * 64 + fq] = vv;
    }

    int og = tid & 15; int o0 = og * 4;
    int ig = tid >> 4;                    // 0..7 -> 4 i's each
    unsigned long long acc[4][2];
#pragma unroll
    for (int t = 0; t < 4; t++) { acc[t][0] = 0ULL; acc[t][1] = 0ULL; }

    for (int kk = 0; kk < KN; kk++) {
        __syncthreads();
#pragma unroll
        for (int p = 0; p < 8; p++) {
            int f = tid + 128 * p;        // float4 index < 1024
            *(float4*)&w_s[f * 4] = *(const float4*)(g_wt + kk * 4096 + f * 4);
        }
        __syncthreads();
#pragma unroll 4
        for (int c = 0; c < 64; c++) {
            ulonglong2 wp = *(const ulonglong2*)&w_s[c * 64 + o0];
#pragma unroll
            for (int t = 0; t < 4; t++) {
                unsigned long long v2 = pack2(v_s[(((ig * 4 + t) * KN) + kk) * 64 + c]);
                fma2(acc[t][0], v2, wp.x);
                fma2(acc[t][1], v2, wp.y);
            }
        }
    }

    float4 cb = *(const float4*)(convb + o0);
    int colbase = (h * 64 + (i0 >> 5)) * Mq + b * Sq;   // d' = i0/32 constant per block
#pragma unroll
    for (int t = 0; t < 4; t++) {
        int il = ig * 4 + t;
        int sp = ((i0 + il) & 31) * 64 + o0;            // s' = (i%32)*64 + o
        float4 o;
        o.x = lo32(acc[t][0]) + cb.x;
        o.y = hi32(acc[t][0]) + cb.y;
        o.z = lo32(acc[t][1]) + cb.z;
        o.w = hi32(acc[t][1]) + cb.w;
        *(float4*)&g_y[colbase + sp] = o;
    }
}

// ---------------- Kernel E: final = y @ Wo^T + b (A = g_y^T, column-major) --
__global__ __launch_bounds__(256, 2) void out_gemm_kernel(
    const float* __restrict__ Wo, const float* __restrict__ bo,
    float* __restrict__ outp)
{
    __shared__ __align__(16) float As[16][132];
    __shared__ __align__(16) float Bs[16][132];

    int m0 = blockIdx.y * 128, n0 = blockIdx.x * 128;
    int tid = threadIdx.x, tx = tid & 15, ty = tid >> 4;
    int r0 = ty * 8, c0 = tx * 8;

    unsigned long long acc[4][8];
#pragma unroll
    for (int i = 0; i < 4; i++)
#pragma unroll
        for (int j = 0; j < 8; j++) acc[i][j] = 0ULL;

    int lrow = tid >> 2, lk = (tid & 3) * 4;
    int fk = tid >> 5, fm = tid & 31;

    for (int k0 = 0; k0 < 512; k0 += 16) {
        float4 a0 = *(const float4*)(g_y + (size_t)(k0 + fk)     * Mq + m0 + fm * 4);
        float4 a1 = *(const float4*)(g_y + (size_t)(k0 + fk + 8) * Mq + m0 + fm * 4);
        float4 b0 = *(const float4*)(Wo + (size_t)(n0 + lrow)      * 512 + k0 + lk);
        float4 b1 = *(const float4*)(Wo + (size_t)(n0 + lrow + 64) * 512 + k0 + lk);
        __syncthreads();
        *(float4*)&As[fk][fm * 4]     = a0;
        *(float4*)&As[fk + 8][fm * 4] = a1;
        Bs[lk+0][lrow] = b0.x; Bs[lk+1][lrow] = b0.y; Bs[lk+2][lrow] = b0.z; Bs[lk+3][lrow] = b0.w;
        Bs[lk+0][lrow+64] = b1.x; Bs[lk+1][lrow+64] = b1.y; Bs[lk+2][lrow+64] = b1.z; Bs[lk+3][lrow+64] = b1.w;
        __syncthreads();
#pragma unroll
        for (int kk = 0; kk < 16; kk++) {
            ulonglong2 ap0 = *(const ulonglong2*)&As[kk][r0];
            ulonglong2 ap1 = *(const ulonglong2*)&As[kk][r0 + 4];
            float4 bv0 = *(const float4*)&Bs[kk][c0];
            float4 bv1 = *(const float4*)&Bs[kk][c0 + 4];
            unsigned long long b2[8];
            b2[0] = pack2(bv0.x); b2[1] = pack2(bv0.y); b2[2] = pack2(bv0.z); b2[3] = pack2(bv0.w);
            b2[4] = pack2(bv1.x); b2[5] = pack2(bv1.y); b2[6] = pack2(bv1.z); b2[7] = pack2(bv1.w);
            unsigned long long a2[4] = {ap0.x, ap0.y, ap1.x, ap1.y};
#pragma unroll
            for (int i = 0; i < 4; i++)
#pragma unroll
                for (int j = 0; j < 8; j++) fma2(acc[i][j], a2[i], b2[j]);
        }
    }

    float4 bias0 = *(const float4*)(bo + n0 + c0);
    float4 bias1 = *(const float4*)(bo + n0 + c0 + 4);
#pragma unroll
    for (int i = 0; i < 4; i++) {
#pragma unroll
        for (int half = 0; half < 2; half++) {
            int m = m0 + r0 + 2 * i + half;
            float4 o0, o1;
            if (half == 0) {
                o0.x = lo32(acc[i][0]) + bias0.x; o0.y = lo32(acc[i][1]) + bias0.y;
                o0.z = lo32(acc[i][2]) + bias0.z; o0.w = lo32(acc[i][3]) + bias0.w;
                o1.x = lo32(acc[i][4]) + bias1.x; o1.y = lo32(acc[i][5]) + bias1.y;
                o1.z = lo32(acc[i][6]) + bias1.z; o1.w = lo32(acc[i][7]) + bias1.w;
            } else {
                o0.x = hi32(acc[i][0]) + bias0.x; o0.y = hi32(acc[i][1]) + bias0.y;
                o0.z = hi32(acc[i][2]) + bias0.z; o0.w = hi32(acc[i][3]) + bias0.w;
                o1.x = hi32(acc[i][4]) + bias1.x; o1.y = hi32(acc[i][5]) + bias1.y;
                o1.z = hi32(acc[i][6]) + bias1.z; o1.w = hi32(acc[i][7]) + bias1.w;
            }
            float* po = outp + (size_t)m * 512 + n0 + c0;
            *(float4*)po = o0;
            *(float4*)(po + 4) = o1;
        }
    }
}

// ---------------- launch -----------------------------------------------------
extern "C" void kernel_launch(void* const* d_in, const int* in_sizes, int n_in,
                              void* d_out, int out_size)
{
    (void)in_sizes; (void)n_in; (void)out_size;
    const float* x      = (const float*)d_in[0];
    const float* Wq_w   = (const float*)d_in[1];
    const float* Wq_b   = (const float*)d_in[2];
    const float* Wk_w   = (const float*)d_in[3];
    const float* Wk_b   = (const float*)d_in[4];
    const float* Wv_w   = (const float*)d_in[5];
    const float* Wv_b   = (const float*)d_in[6];
    const float* Wo_w   = (const float*)d_in[7];
    const float* Wo_b   = (const float*)d_in[8];
    const float* conv_w = (const float*)d_in[9];
    const float* conv_b = (const float*)d_in[10];
    float* outp = (float*)d_out;

    const int SMEM_C = (64 * 128 + 64 * 64 + 128 * 68) * 4;  // 83968 B
    const int SMEM_D = (288 * 64 + 64 * 64) * 4 + 288 * 4;   // 91264 B
    cudaFuncSetAttribute(sim_topk_kernel, cudaFuncAttributeMaxDynamicSharedMemorySize, SMEM_C);
    cudaFuncSetAttribute(conv_kernel,     cudaFuncAttributeMaxDynamicSharedMemorySize, SMEM_D);

    qkv_gemm_kernel<<<dim3(4, 64, 3), 256>>>(x, Wq_w, Wq_b, Wk_w, Wk_b, Wv_w, Wv_b);
    normalize_kernel<<<16384, 256>>>();
    transpose_convw_kernel<<<144, 256>>>(conv_w);
    sim_topk_kernel<<<dim3(16, 32), 256, SMEM_C>>>();
    conv_kernel<<<dim3(64, 32), 128, SMEM_D>>>(conv_b);
    out_gemm_kernel<<<dim3(4, 64), 256>>>(Wo_w, Wo_b, outp);
}

// round 4
// speedup vs baseline: 1.1677x; 1.0320x over previous
#include <cuda_runtime.h>
#include <math.h>

#define Bq   4
#define Sq   2048
#define Dq   512
#define Hq   8
#define DKq  64
#define KN   9
#define BHq  32
#define Mq   8192   /* B*S */
#define EPSN 1e-12f

// ---------------- packed fp32x2 helpers (sm_103a FFMA2) ----------------
__device__ __forceinline__ unsigned long long pack2(float x) {
    unsigned long long r;
    asm("mov.b64 %0, {%1, %1};" : "=l"(r) : "f"(x));
    return r;
}
__device__ __forceinline__ void fma2(unsigned long long& d,
                                     unsigned long long a, unsigned long long b) {
    asm("fma.rn.f32x2 %0, %1, %2, %0;" : "+l"(d) : "l"(a), "l"(b));
}
__device__ __forceinline__ float lo32(unsigned long long v) {
    return __uint_as_float((unsigned)v);
}
__device__ __forceinline__ float hi32(unsigned long long v) {
    return __uint_as_float((unsigned)(v >> 32));
}

// ---------------- scratch (device globals; no allocation) ----------------
__device__ float g_q[BHq * Sq * DKq];      // [bh][s][c]
__device__ float g_k[BHq * Sq * DKq];
__device__ float g_v[BHq * Sq * DKq];
__device__ int   g_idx[BHq * Sq * KN];     // top-9 indices, sorted desc by sim
__device__ float g_y[Dq * Mq];             // y^T: [col][b*S + s']
__device__ float g_wt[KN * DKq * DKq];     // Wt[kk][c][o]

// ---------------- Kernel A: QKV GEMM  out = x @ W^T + b, split-head layout ----
// software-pipelined: LDG for k-tile t+1 issued before compute of tile t
__global__ __launch_bounds__(256, 2) void qkv_gemm_kernel(
    const float* __restrict__ x,
    const float* __restrict__ Wq, const float* __restrict__ bq,
    const float* __restrict__ Wk, const float* __restrict__ bk,
    const float* __restrict__ Wv, const float* __restrict__ bv)
{
    __shared__ __align__(16) float As[16][132];
    __shared__ __align__(16) float Bs[16][132];

    const float* W; const float* bias; float* out;
    int z = blockIdx.z;
    if (z == 0)      { W = Wq; bias = bq; out = g_q; }
    else if (z == 1) { W = Wk; bias = bk; out = g_k; }
    else             { W = Wv; bias = bv; out = g_v; }

    int m0 = blockIdx.y * 128;
    int n0 = blockIdx.x * 128;
    int tid = threadIdx.x;
    int tx = tid & 15, ty = tid >> 4;
    int r0 = ty * 8, c0 = tx * 8;

    unsigned long long acc[4][8];
#pragma unroll
    for (int i = 0; i < 4; i++)
#pragma unroll
        for (int j = 0; j < 8; j++) acc[i][j] = 0ULL;

    int lrow = tid >> 2;
    int lk   = (tid & 3) * 4;

    const float* pa0 = x + (size_t)(m0 + lrow)      * 512 + lk;
    const float* pa1 = x + (size_t)(m0 + lrow + 64) * 512 + lk;
    const float* pb0 = W + (size_t)(n0 + lrow)      * 512 + lk;
    const float* pb1 = W + (size_t)(n0 + lrow + 64) * 512 + lk;

    float4 a0 = *(const float4*)(pa0);
    float4 a1 = *(const float4*)(pa1);
    float4 b0 = *(const float4*)(pb0);
    float4 b1 = *(const float4*)(pb1);

    for (int k0 = 0; k0 < 512; k0 += 16) {
        __syncthreads();
        As[lk+0][lrow] = a0.x; As[lk+1][lrow] = a0.y; As[lk+2][lrow] = a0.z; As[lk+3][lrow] = a0.w;
        As[lk+0][lrow+64] = a1.x; As[lk+1][lrow+64] = a1.y; As[lk+2][lrow+64] = a1.z; As[lk+3][lrow+64] = a1.w;
        Bs[lk+0][lrow] = b0.x; Bs[lk+1][lrow] = b0.y; Bs[lk+2][lrow] = b0.z; Bs[lk+3][lrow] = b0.w;
        Bs[lk+0][lrow+64] = b1.x; Bs[lk+1][lrow+64] = b1.y; Bs[lk+2][lrow+64] = b1.z; Bs[lk+3][lrow+64] = b1.w;
        __syncthreads();
        if (k0 + 16 < 512) {
            a0 = *(const float4*)(pa0 + k0 + 16);
            a1 = *(const float4*)(pa1 + k0 + 16);
            b0 = *(const float4*)(pb0 + k0 + 16);
            b1 = *(const float4*)(pb1 + k0 + 16);
        }
#pragma unroll
        for (int kk = 0; kk < 16; kk++) {
            ulonglong2 ap0 = *(const ulonglong2*)&As[kk][r0];
            ulonglong2 ap1 = *(const ulonglong2*)&As[kk][r0 + 4];
            float4 bv0 = *(const float4*)&Bs[kk][c0];
            float4 bv1 = *(const float4*)&Bs[kk][c0 + 4];
            unsigned long long b2[8];
            b2[0] = pack2(bv0.x); b2[1] = pack2(bv0.y); b2[2] = pack2(bv0.z); b2[3] = pack2(bv0.w);
            b2[4] = pack2(bv1.x); b2[5] = pack2(bv1.y); b2[6] = pack2(bv1.z); b2[7] = pack2(bv1.w);
            unsigned long long a2[4] = {ap0.x, ap0.y, ap1.x, ap1.y};
#pragma unroll
            for (int i = 0; i < 4; i++)
#pragma unroll
                for (int j = 0; j < 8; j++) fma2(acc[i][j], a2[i], b2[j]);
        }
    }

    float4 bias0 = *(const float4*)(bias + n0 + c0);
    float4 bias1 = *(const float4*)(bias + n0 + c0 + 4);
    int n = n0 + c0;
    int h = n >> 6, c = n & 63;
#pragma unroll
    for (int i = 0; i < 4; i++) {
#pragma unroll
        for (int half = 0; half < 2; half++) {
            int m = m0 + r0 + 2 * i + half;
            int bb = m >> 11;
            int s  = m & 2047;
            float4 o0, o1;
            if (half == 0) {
                o0.x = lo32(acc[i][0]) + bias0.x; o0.y = lo32(acc[i][1]) + bias0.y;
                o0.z = lo32(acc[i][2]) + bias0.z; o0.w = lo32(acc[i][3]) + bias0.w;
                o1.x = lo32(acc[i][4]) + bias1.x; o1.y = lo32(acc[i][5]) + bias1.y;
                o1.z = lo32(acc[i][6]) + bias1.z; o1.w = lo32(acc[i][7]) + bias1.w;
            } else {
                o0.x = hi32(acc[i][0]) + bias0.x; o0.y = hi32(acc[i][1]) + bias0.y;
                o0.z = hi32(acc[i][2]) + bias0.z; o0.w = hi32(acc[i][3]) + bias0.w;
                o1.x = hi32(acc[i][4]) + bias1.x; o1.y = hi32(acc[i][5]) + bias1.y;
                o1.z = hi32(acc[i][6]) + bias1.z; o1.w = hi32(acc[i][7]) + bias1.w;
            }
            float* po = out + ((size_t)(bb * Hq + h) * Sq + s) * DKq + c;
            *(float4*)po = o0;
            *(float4*)(po + 4) = o1;
        }
    }
}

// ---------------- Kernel B: L2-normalize q and k rows (over dk=64) ----------
__global__ __launch_bounds__(256) void normalize_kernel()
{
    int gw   = blockIdx.x * 8 + (threadIdx.x >> 5);
    int lane = threadIdx.x & 31;
    float* p;
    if (gw < BHq * Sq) p = g_k + (size_t)gw * 64;
    else               p = g_q + (size_t)(gw - BHq * Sq) * 64;
    float v0 = p[lane], v1 = p[lane + 32];
    float ss = v0 * v0 + v1 * v1;
#pragma unroll
    for (int o = 16; o; o >>= 1) ss += __shfl_xor_sync(0xffffffffu, ss, o);
    float inv = 1.0f / fmaxf(sqrtf(ss), EPSN);
    p[lane] = v0 * inv; p[lane + 32] = v1 * inv;
}

// ---------------- Kernel C: fused sim GEMM + ReLU + streaming top-9 ---------
// grid (S/128, BH); 256 threads; 2 blocks/SM; Bs loads software-pipelined.
__global__ __launch_bounds__(256, 2) void sim_topk_kernel()
{
    extern __shared__ __align__(16) float sm[];
    float* As = sm;              // 64*128 = 8192
    float* Bs = sm + 8192;       // 64*64  = 4096
    float* Ss = sm + 12288;      // 128*68 = 8704

    int bh = blockIdx.y;
    int i0 = blockIdx.x * 128;
    int tid = threadIdx.x;
    int tx = tid & 15, ty = tid >> 4;
    int r0 = ty * 8, c0 = tx * 4;

    const float* kbase = g_k + (size_t)bh * Sq * DKq;
    const float* qbase = g_q + (size_t)bh * Sq * DKq;

    // fill As (kn tile, transposed + swizzled), once
#pragma unroll
    for (int p = 0; p < 8; p++) {
        int f = tid + 256 * p;
        int r = f >> 4, dq = (f & 15) * 4;
        float4 v = *(const float4*)(kbase + (size_t)(i0 + r) * 64 + dq);
        int pr = r ^ (((dq >> 2) & 7) << 3);
        As[(dq + 0) * 128 + pr] = v.x;
        As[(dq + 1) * 128 + pr] = v.y;
        As[(dq + 2) * 128 + pr] = v.z;
        As[(dq + 3) * 128 + pr] = v.w;
    }

    float tv[9]; int ti[9];
#pragma unroll
    for (int q = 0; q < 9; q++) { tv[q] = -1.0f; ti[q] = 0; }

    int row = tid >> 1, part = tid & 1;
    int brow = tid >> 4, bdq = (tid & 15) * 4;
    const float* bptr = qbase + (size_t)brow * 64 + bdq;
    int bpr = brow ^ (((bdq >> 2) & 7) << 3);

    // prefetch first Bs tile
    float4 br[4];
#pragma unroll
    for (int p = 0; p < 4; p++)
        br[p] = *(const float4*)(bptr + (size_t)(16 * p) * 64);

    for (int j0 = 0; j0 < Sq; j0 += 64) {
        __syncthreads();
        // store staged Bs tile (transposed + swizzled)
#pragma unroll
        for (int p = 0; p < 4; p++) {
            int pr = (bpr + 16 * p);   // row index increments by 16, swizzle on row bits 3-5
            int rr = (brow + 16 * p) ^ (((bdq >> 2) & 7) << 3);
            Bs[(bdq + 0) * 64 + rr] = br[p].x;
            Bs[(bdq + 1) * 64 + rr] = br[p].y;
            Bs[(bdq + 2) * 64 + rr] = br[p].z;
            Bs[(bdq + 3) * 64 + rr] = br[p].w;
            (void)pr;
        }
        __syncthreads();
        // prefetch next Bs tile
        if (j0 + 64 < Sq) {
#pragma unroll
            for (int p = 0; p < 4; p++)
                br[p] = *(const float4*)(bptr + (size_t)(j0 + 64 + 16 * p) * 64);
        }

        unsigned long long acc[4][4];
#pragma unroll
        for (int i = 0; i < 4; i++)
#pragma unroll
            for (int j = 0; j < 4; j++) acc[i][j] = 0ULL;

#pragma unroll 8
        for (int kk = 0; kk < 64; kk++) {
            int swz = ((kk >> 2) & 7) << 3;
            ulonglong2 ap0 = *(const ulonglong2*)&As[kk * 128 + (r0 ^ swz)];
            ulonglong2 ap1 = *(const ulonglong2*)&As[kk * 128 + (r0 ^ swz) + 4];
            float4 bv = *(const float4*)&Bs[kk * 64 + (c0 ^ swz)];
            unsigned long long b2[4];
            b2[0] = pack2(bv.x); b2[1] = pack2(bv.y);
            b2[2] = pack2(bv.z); b2[3] = pack2(bv.w);
            unsigned long long a2[4] = {ap0.x, ap0.y, ap1.x, ap1.y};
#pragma unroll
            for (int i = 0; i < 4; i++)
#pragma unroll
                for (int j = 0; j < 4; j++) fma2(acc[i][j], a2[i], b2[j]);
        }

        // write ReLU'd tile: rows r0..r0+7, cols c0..c0+3
#pragma unroll
        for (int i = 0; i < 4; i++) {
            float4 oL, oH;
            oL.x = fmaxf(lo32(acc[i][0]), 0.0f);
            oL.y = fmaxf(lo32(acc[i][1]), 0.0f);
            oL.z = fmaxf(lo32(acc[i][2]), 0.0f);
            oL.w = fmaxf(lo32(acc[i][3]), 0.0f);
            oH.x = fmaxf(hi32(acc[i][0]), 0.0f);
            oH.y = fmaxf(hi32(acc[i][1]), 0.0f);
            oH.z = fmaxf(hi32(acc[i][2]), 0.0f);
            oH.w = fmaxf(hi32(acc[i][3]), 0.0f);
            *(float4*)&Ss[(r0 + 2 * i)     * 68 + c0] = oL;
            *(float4*)&Ss[(r0 + 2 * i + 1) * 68 + c0] = oH;
        }
        __syncthreads();

        // streaming top-9: this thread covers cols [part*32, part*32+32)
#pragma unroll
        for (int t = 0; t < 8; t++) {
            float4 v4 = *(const float4*)&Ss[row * 68 + part * 32 + t * 4];
            int cb = j0 + part * 32 + t * 4;
            float vv[4] = {v4.x, v4.y, v4.z, v4.w};
#pragma unroll
            for (int u = 0; u < 4; u++) {
                float v = vv[u];
                if (v > tv[8]) {
                    tv[8] = v; ti[8] = cb + u;
#pragma unroll
                    for (int q = 8; q > 0; q--) {
                        if (tv[q] > tv[q - 1]) {
                            float tf = tv[q]; tv[q] = tv[q - 1]; tv[q - 1] = tf;
                            int tt = ti[q]; ti[q] = ti[q - 1]; ti[q - 1] = tt;
                        }
                    }
                }
            }
        }
    }
    __syncthreads();

    // merge 2 per-row lists (alias As region)
    float* Mv = sm;                      // 256*9 floats
    int*   Mi = (int*)(sm + 2304);       // 256*9 ints
#pragma unroll
    for (int q = 0; q < 9; q++) {
        Mv[(row * 2 + part) * 9 + q] = tv[q];
        Mi[(row * 2 + part) * 9 + q] = ti[q];
    }
    __syncthreads();
    if (tid < 128) {
        int p0 = 0, p1 = 0;
        const float* L0v = Mv + (tid * 2) * 9;
        const float* L1v = Mv + (tid * 2 + 1) * 9;
        const int*   L0i = Mi + (tid * 2) * 9;
        const int*   L1i = Mi + (tid * 2 + 1) * 9;
        int obase = (bh * Sq + i0 + tid) * KN;
#pragma unroll
        for (int kk = 0; kk < KN; kk++) {
            float v0 = L0v[p0], v1 = L1v[p1];
            int ix0 = L0i[p0], ix1 = L1i[p1];
            bool take0 = (v0 > v1) || (v0 == v1 && ix0 < ix1);
            g_idx[obase + kk] = take0 ? ix0 : ix1;
            if (take0) p0++; else p1++;
        }
    }
}

// ---------------- prep: transpose conv_w [o][c][kk] -> Wt[kk][c][o] ---------
__global__ void transpose_convw_kernel(const float* __restrict__ w)
{
    int t = blockIdx.x * 256 + threadIdx.x;
    if (t < KN * DKq * DKq) {
        int o = t & 63, c = (t >> 6) & 63, kk = t >> 12;
        g_wt[t] = w[(o * 64 + c) * KN + kk];
    }
}

// ---------------- Kernel D: gather v by idx + grouped conv, scatter to y^T --
// grid (S/32, BH); 128 threads; w_s kk-loop software-pipelined.
__global__ __launch_bounds__(128, 2) void conv_kernel(const float* __restrict__ convb)
{
    extern __shared__ float smd[];
    float* v_s  = smd;                   // [288][64]
    float* w_s  = smd + 288 * 64;        // [64 c][64 o]
    int*   sidx = (int*)(smd + 288 * 64 + 4096);  // [288]

    int bh = blockIdx.y;
    int i0 = blockIdx.x * 32;
    int b  = bh >> 3, h = bh & 7;
    int tid = threadIdx.x;

    for (int t = tid; t < 288; t += 128)
        sidx[t] = g_idx[(bh * Sq + i0 + t / KN) * KN + (t % KN)];

    // prefetch kk=0 weights while idx/gather in flight
    float4 wreg[8];
#pragma unroll
    for (int p = 0; p < 8; p++)
        wreg[p] = *(const float4*)(g_wt + (tid + 128 * p) * 4);

    __syncthreads();

    const float* vbase = g_v + (size_t)bh * Sq * DKq;
    for (int p = 0; p < 36; p++) {
        int f = tid + 128 * p;           // 4608 float4s total
        int r = f >> 4, fq = (f & 15) * 4;
        int j = sidx[r];
        float4 vv = *(const float4*)(vbase + (size_t)j * 64 + fq);
        *(float4*)&v_s[r * 64 + fq] = vv;
    }

    int og = tid & 15; int o0 = og * 4;
    int ig = tid >> 4;                    // 0..7 -> 4 i's each
    unsigned long long acc[4][2];
#pragma unroll
    for (int t = 0; t < 4; t++) { acc[t][0] = 0ULL; acc[t][1] = 0ULL; }

    for (int kk = 0; kk < KN; kk++) {
        __syncthreads();
#pragma unroll
        for (int p = 0; p < 8; p++)
            *(float4*)&w_s[(tid + 128 * p) * 4] = wreg[p];
        __syncthreads();
        if (kk + 1 < KN) {
#pragma unroll
            for (int p = 0; p < 8; p++)
                wreg[p] = *(const float4*)(g_wt + (kk + 1) * 4096 + (tid + 128 * p) * 4);
        }
#pragma unroll 4
        for (int c = 0; c < 64; c++) {
            ulonglong2 wp = *(const ulonglong2*)&w_s[c * 64 + o0];
#pragma unroll
            for (int t = 0; t < 4; t++) {
                unsigned long long v2 = pack2(v_s[(((ig * 4 + t) * KN) + kk) * 64 + c]);
                fma2(acc[t][0], v2, wp.x);
                fma2(acc[t][1], v2, wp.y);
            }
        }
    }

    float4 cb = *(const float4*)(convb + o0);
    int colbase = (h * 64 + (i0 >> 5)) * Mq + b * Sq;   // d' = i0/32 constant per block
#pragma unroll
    for (int t = 0; t < 4; t++) {
        int il = ig * 4 + t;
        int sp = ((i0 + il) & 31) * 64 + o0;            // s' = (i%32)*64 + o
        float4 o;
        o.x = lo32(acc[t][0]) + cb.x;
        o.y = hi32(acc[t][0]) + cb.y;
        o.z = lo32(acc[t][1]) + cb.z;
        o.w = hi32(acc[t][1]) + cb.w;
        *(float4*)&g_y[colbase + sp] = o;
    }
}

// ---------------- Kernel E: final = y @ Wo^T + b (A = g_y^T, column-major) --
__global__ __launch_bounds__(256, 2) void out_gemm_kernel(
    const float* __restrict__ Wo, const float* __restrict__ bo,
    float* __restrict__ outp)
{
    __shared__ __align__(16) float As[16][132];
    __shared__ __align__(16) float Bs[16][132];

    int m0 = blockIdx.y * 128, n0 = blockIdx.x * 128;
    int tid = threadIdx.x, tx = tid & 15, ty = tid >> 4;
    int r0 = ty * 8, c0 = tx * 8;

    unsigned long long acc[4][8];
#pragma unroll
    for (int i = 0; i < 4; i++)
#pragma unroll
        for (int j = 0; j < 8; j++) acc[i][j] = 0ULL;

    int lrow = tid >> 2, lk = (tid & 3) * 4;
    int fk = tid >> 5, fm = tid & 31;

    const float* pa0 = g_y + (size_t)fk * Mq + m0 + fm * 4;
    const float* pa1 = g_y + (size_t)(fk + 8) * Mq + m0 + fm * 4;
    const float* pb0 = Wo + (size_t)(n0 + lrow)      * 512 + lk;
    const float* pb1 = Wo + (size_t)(n0 + lrow + 64) * 512 + lk;

    float4 a0 = *(const float4*)(pa0);
    float4 a1 = *(const float4*)(pa1);
    float4 b0 = *(const float4*)(pb0);
    float4 b1 = *(const float4*)(pb1);

    for (int k0 = 0; k0 < 512; k0 += 16) {
        __syncthreads();
        *(float4*)&As[fk][fm * 4]     = a0;
        *(float4*)&As[fk + 8][fm * 4] = a1;
        Bs[lk+0][lrow] = b0.x; Bs[lk+1][lrow] = b0.y; Bs[lk+2][lrow] = b0.z; Bs[lk+3][lrow] = b0.w;
        Bs[lk+0][lrow+64] = b1.x; Bs[lk+1][lrow+64] = b1.y; Bs[lk+2][lrow+64] = b1.z; Bs[lk+3][lrow+64] = b1.w;
        __syncthreads();
        if (k0 + 16 < 512) {
            a0 = *(const float4*)(pa0 + (size_t)(k0 + 16) * Mq);
            a1 = *(const float4*)(pa1 + (size_t)(k0 + 16) * Mq);
            b0 = *(const float4*)(pb0 + k0 + 16);
            b1 = *(const float4*)(pb1 + k0 + 16);
        }
#pragma unroll
        for (int kk = 0; kk < 16; kk++) {
            ulonglong2 ap0 = *(const ulonglong2*)&As[kk][r0];
            ulonglong2 ap1 = *(const ulonglong2*)&As[kk][r0 + 4];
            float4 bv0 = *(const float4*)&Bs[kk][c0];
            float4 bv1 = *(const float4*)&Bs[kk][c0 + 4];
            unsigned long long b2[8];
            b2[0] = pack2(bv0.x); b2[1] = pack2(bv0.y); b2[2] = pack2(bv0.z); b2[3] = pack2(bv0.w);
            b2[4] = pack2(bv1.x); b2[5] = pack2(bv1.y); b2[6] = pack2(bv1.z); b2[7] = pack2(bv1.w);
            unsigned long long a2[4] = {ap0.x, ap0.y, ap1.x, ap1.y};
#pragma unroll
            for (int i = 0; i < 4; i++)
#pragma unroll
                for (int j = 0; j < 8; j++) fma2(acc[i][j], a2[i], b2[j]);
        }
    }

    float4 bias0 = *(const float4*)(bo + n0 + c0);
    float4 bias1 = *(const float4*)(bo + n0 + c0 + 4);
#pragma unroll
    for (int i = 0; i < 4; i++) {
#pragma unroll
        for (int half = 0; half < 2; half++) {
            int m = m0 + r0 + 2 * i + half;
            float4 o0, o1;
            if (half == 0) {
                o0.x = lo32(acc[i][0]) + bias0.x; o0.y = lo32(acc[i][1]) + bias0.y;
                o0.z = lo32(acc[i][2]) + bias0.z; o0.w = lo32(acc[i][3]) + bias0.w;
                o1.x = lo32(acc[i][4]) + bias1.x; o1.y = lo32(acc[i][5]) + bias1.y;
                o1.z = lo32(acc[i][6]) + bias1.z; o1.w = lo32(acc[i][7]) + bias1.w;
            } else {
                o0.x = hi32(acc[i][0]) + bias0.x; o0.y = hi32(acc[i][1]) + bias0.y;
                o0.z = hi32(acc[i][2]) + bias0.z; o0.w = hi32(acc[i][3]) + bias0.w;
                o1.x = hi32(acc[i][4]) + bias1.x; o1.y = hi32(acc[i][5]) + bias1.y;
                o1.z = hi32(acc[i][6]) + bias1.z; o1.w = hi32(acc[i][7]) + bias1.w;
            }
            float* po = outp + (size_t)m * 512 + n0 + c0;
            *(float4*)po = o0;
            *(float4*)(po + 4) = o1;
        }
    }
}

// ---------------- launch -----------------------------------------------------
extern "C" void kernel_launch(void* const* d_in, const int* in_sizes, int n_in,
                              void* d_out, int out_size)
{
    (void)in_sizes; (void)n_in; (void)out_size;
    const float* x      = (const float*)d_in[0];
    const float* Wq_w   = (const float*)d_in[1];
    const float* Wq_b   = (const float*)d_in[2];
    const float* Wk_w   = (const float*)d_in[3];
    const float* Wk_b   = (const float*)d_in[4];
    const float* Wv_w   = (const float*)d_in[5];
    const float* Wv_b   = (const float*)d_in[6];
    const float* Wo_w   = (const float*)d_in[7];
    const float* Wo_b   = (const float*)d_in[8];
    const float* conv_w = (const float*)d_in[9];
    const float* conv_b = (const float*)d_in[10];
    float* outp = (float*)d_out;

    const int SMEM_C = (64 * 128 + 64 * 64 + 128 * 68) * 4;  // 83968 B
    const int SMEM_D = (288 * 64 + 64 * 64) * 4 + 288 * 4;   // 91264 B
    cudaFuncSetAttribute(sim_topk_kernel, cudaFuncAttributeMaxDynamicSharedMemorySize, SMEM_C);
    cudaFuncSetAttribute(conv_kernel,     cudaFuncAttributeMaxDynamicSharedMemorySize, SMEM_D);

    qkv_gemm_kernel<<<dim3(4, 64, 3), 256>>>(x, Wq_w, Wq_b, Wk_w, Wk_b, Wv_w, Wv_b);
    normalize_kernel<<<16384, 256>>>();
    transpose_convw_kernel<<<144, 256>>>(conv_w);
    sim_topk_kernel<<<dim3(16, 32), 256, SMEM_C>>>();
    conv_kernel<<<dim3(64, 32), 128, SMEM_D>>>(conv_b);
    out_gemm_kernel<<<dim3(4, 64), 256>>>(Wo_w, Wo_b, outp);
}